// round 8
// baseline (speedup 1.0000x reference)
#include <cuda_runtime.h>
#include <cuda_fp16.h>

#define N_NODES 50000
#define F 64
#define HDIM 128          // h1 (64) and h2 (64) interleaved per node, fp16
#define BSTRIDE 128       // bucket region per node (4 reps x 32 cap)
#define BCAP 32
#define NREP 4

// Scratch: __device__ globals (allocation-free, graph-capturable).
// Invariant: g_cursor is all-zero at kernel_launch entry (zero at module load;
// agg_kernel re-zeroes after reading, every run).
__device__ __align__(16) __half g_h[(size_t)N_NODES * HDIM];     // [N][128] fp16
__device__ float g_dinv[N_NODES];
__device__ float g_invdeg[N_NODES];
__device__ __align__(16) int g_cursor[NREP * N_NODES];           // per (node, rep)
__device__ int g_srcsorted[(size_t)N_NODES * BSTRIDE];           // bucketed src ids

// ---------------------------------------------------------------------------
// Fused kernel: blocks [0, nScatter) run the edge bucket-scatter (L2-bound),
// blocks [nScatter, ...) run the HMMA dual-GEMM (tensor/smem-bound).
// The two partitions are independent and overlap on different pipes.
// ---------------------------------------------------------------------------
__global__ void __launch_bounds__(256) fused_kernel(
    const float* __restrict__ x,
    const float* __restrict__ W1,
    const float* __restrict__ W2,
    const int* __restrict__ ei, int E, int nScatter) {

    __shared__ __half xs[128][72];
    __shared__ __half ws[128][72];

    int tid = threadIdx.x;

    if (blockIdx.x < (unsigned)nScatter) {
        // ----------------- scatter partition -----------------
        int t = blockIdx.x * 256 + tid;
        int rep = t & (NREP - 1);
        int base = t * 4;
        if (base + 4 <= E) {
            int4 s = *(const int4*)(ei + base);
            int4 d = *(const int4*)(ei + E + base);
            int p0 = atomicAdd(&g_cursor[d.x * NREP + rep], 1);
            int p1 = atomicAdd(&g_cursor[d.y * NREP + rep], 1);
            int p2 = atomicAdd(&g_cursor[d.z * NREP + rep], 1);
            int p3 = atomicAdd(&g_cursor[d.w * NREP + rep], 1);
            g_srcsorted[(size_t)d.x * BSTRIDE + rep * BCAP + p0] = s.x;
            g_srcsorted[(size_t)d.y * BSTRIDE + rep * BCAP + p1] = s.y;
            g_srcsorted[(size_t)d.z * BSTRIDE + rep * BCAP + p2] = s.z;
            g_srcsorted[(size_t)d.w * BSTRIDE + rep * BCAP + p3] = s.w;
        } else {
            for (int e = base; e < E; e++) {
                int d = ei[E + e];
                int pos = atomicAdd(&g_cursor[d * NREP + rep], 1);
                g_srcsorted[(size_t)d * BSTRIDE + rep * BCAP + pos] = ei[e];
            }
        }
        return;
    }

    // ----------------- gemm partition -----------------
    int gb = blockIdx.x - nScatter;
    int row0 = gb * 128;

    // Load x tile (f32 -> fp16 into smem), coalesced float4 reads.
    for (int i = tid; i < 128 * 16; i += 256) {
        int r = i >> 4, c4 = i & 15;
        int row = row0 + r;
        float4 v = make_float4(0.f, 0.f, 0.f, 0.f);
        if (row < N_NODES) v = *(const float4*)(x + (size_t)row * F + c4 * 4);
        __half2 h0 = __floats2half2_rn(v.x, v.y);
        __half2 h1 = __floats2half2_rn(v.z, v.w);
        uint2 o = make_uint2(*reinterpret_cast<unsigned*>(&h0),
                             *reinterpret_cast<unsigned*>(&h1));
        *(uint2*)&xs[r][c4 * 4] = o;
    }
    // Load W (f32, coalesced) -> ws[c][k] fp16 (n-major, transposed in smem).
    for (int i = tid; i < 128 * 64; i += 256) {
        int k = i >> 7, c = i & 127;
        float v = (c < 64) ? W1[k * 64 + c] : W2[k * 64 + (c - 64)];
        ws[c][k] = __float2half_rn(v);
    }
    __syncthreads();

    int warp = tid >> 5, lane = tid & 31;
    int g = lane >> 2, t = lane & 3;
    int wrow = warp * 16;

    float c[16][4];
    #pragma unroll
    for (int nt = 0; nt < 16; nt++)
        #pragma unroll
        for (int j = 0; j < 4; j++) c[nt][j] = 0.0f;

    #pragma unroll
    for (int ks = 0; ks < 4; ks++) {
        int kb = ks * 16;
        unsigned a0 = *(const unsigned*)&xs[wrow + g][kb + 2 * t];
        unsigned a1 = *(const unsigned*)&xs[wrow + g + 8][kb + 2 * t];
        unsigned a2 = *(const unsigned*)&xs[wrow + g][kb + 2 * t + 8];
        unsigned a3 = *(const unsigned*)&xs[wrow + g + 8][kb + 2 * t + 8];
        #pragma unroll
        for (int nt = 0; nt < 16; nt++) {
            unsigned b0 = *(const unsigned*)&ws[nt * 8 + g][kb + 2 * t];
            unsigned b1 = *(const unsigned*)&ws[nt * 8 + g][kb + 2 * t + 8];
            asm volatile(
                "mma.sync.aligned.m16n8k16.row.col.f32.f16.f16.f32 "
                "{%0,%1,%2,%3}, {%4,%5,%6,%7}, {%8,%9}, {%0,%1,%2,%3};"
                : "+f"(c[nt][0]), "+f"(c[nt][1]), "+f"(c[nt][2]), "+f"(c[nt][3])
                : "r"(a0), "r"(a1), "r"(a2), "r"(a3), "r"(b0), "r"(b1));
        }
    }

    int r1 = row0 + wrow + g;
    int r2 = r1 + 8;
    #pragma unroll
    for (int nt = 0; nt < 16; nt++) {
        int col = nt * 8 + 2 * t;
        if (r1 < N_NODES) {
            __half2 h = __floats2half2_rn(c[nt][0], c[nt][1]);
            *(__half2*)(g_h + (size_t)r1 * HDIM + col) = h;
        }
        if (r2 < N_NODES) {
            __half2 h = __floats2half2_rn(c[nt][2], c[nt][3]);
            *(__half2*)(g_h + (size_t)r2 * HDIM + col) = h;
        }
    }
}

// ---------------------------------------------------------------------------
// deg = sum of 4 cursors + 1 (self loop) -> dinv, invdeg.
// ---------------------------------------------------------------------------
__global__ void dinv_kernel() {
    int i = blockIdx.x * blockDim.x + threadIdx.x;
    if (i < N_NODES) {
        int4 c = *(const int4*)(g_cursor + i * NREP);
        float dg = (float)(c.x + c.y + c.z + c.w + 1);
        g_invdeg[i] = 1.0f / dg;
        g_dinv[i]   = rsqrtf(dg);
    }
}

// ---------------------------------------------------------------------------
// Aggregation: one warp per destination node. Lane l owns cols 4l..4l+3.
// 4 bucket segments (<=32 each); lanes pre-load src+norm (padded lanes get
// nrm=0, src=node), then fixed-8-unrolled broadcast subchunks.
// Re-zeroes this node's cursors at the end (restores the entry invariant).
// ---------------------------------------------------------------------------
__global__ void agg_kernel(float* __restrict__ out) {
    int node = (blockIdx.x * blockDim.x + threadIdx.x) >> 5;
    int lane = threadIdx.x & 31;
    if (node >= N_NODES) return;

    float di = g_dinv[node];
    int4 cc = *(const int4*)(g_cursor + node * NREP);
    if (lane == 0)
        *(int4*)(g_cursor + node * NREP) = make_int4(0, 0, 0, 0);
    int cnt_arr[4] = {cc.x, cc.y, cc.z, cc.w};

    // self-loop term: di*di * h[node]
    float ax, ay, az, aw;
    {
        uint2 v = *((const uint2*)(g_h + (size_t)node * HDIM) + lane);
        float2 f0 = __half22float2(*reinterpret_cast<__half2*>(&v.x));
        float2 f1 = __half22float2(*reinterpret_cast<__half2*>(&v.y));
        float self = di * di;
        ax = self * f0.x; ay = self * f0.y; az = self * f1.x; aw = self * f1.y;
    }

    #pragma unroll
    for (int rep = 0; rep < NREP; rep++) {
        int cnt = cnt_arr[rep];
        const int* src = g_srcsorted + (size_t)node * BSTRIDE + rep * BCAP;

        int   sv = node; float nv = 0.0f;
        if (lane < cnt) { sv = src[lane]; nv = di * g_dinv[sv]; }

        int nsub = (cnt + 7) >> 3;
        for (int sub = 0; sub < nsub; sub++) {
            int off = sub * 8;
            #pragma unroll
            for (int u = 0; u < 8; u++) {
                int   ss = __shfl_sync(0xffffffffu, sv, off + u);
                float nn = __shfl_sync(0xffffffffu, nv, off + u);
                uint2 v = *((const uint2*)(g_h + (size_t)ss * HDIM) + lane);
                float2 f0 = __half22float2(*reinterpret_cast<__half2*>(&v.x));
                float2 f1 = __half22float2(*reinterpret_cast<__half2*>(&v.y));
                ax = fmaf(nn, f0.x, ax);
                ay = fmaf(nn, f0.y, ay);
                az = fmaf(nn, f1.x, az);
                aw = fmaf(nn, f1.y, aw);
            }
        }
    }

    float inv = g_invdeg[node];
    ax *= inv; ay *= inv; az *= inv; aw *= inv;

    // lanes 0-15 hold layer1 (cols 0..63), lanes 16-31 hold layer2 (cols 64..127)
    int peer = (lane < 16) ? lane + 16 : lane;
    float bx = __shfl_sync(0xffffffffu, ax, peer);
    float by = __shfl_sync(0xffffffffu, ay, peer);
    float bz = __shfl_sync(0xffffffffu, az, peer);
    float bw = __shfl_sync(0xffffffffu, aw, peer);

    if (lane < 16) {
        float4 o;
        o.x = fmaxf(ax, 0.0f) * (1.0f / (1.0f + expf(-bx)));
        o.y = fmaxf(ay, 0.0f) * (1.0f / (1.0f + expf(-by)));
        o.z = fmaxf(az, 0.0f) * (1.0f / (1.0f + expf(-bz)));
        o.w = fmaxf(aw, 0.0f) * (1.0f / (1.0f + expf(-bw)));
        *((float4*)(out + (size_t)node * F) + lane) = o;
    }
}

// ---------------------------------------------------------------------------
extern "C" void kernel_launch(void* const* d_in, const int* in_sizes, int n_in,
                              void* d_out, int out_size) {
    const float* x  = (const float*)d_in[0];
    const int*   ei = (const int*)d_in[1];   // int32 (JAX x64 disabled)
    const float* W1 = (const float*)d_in[2];
    const float* W2 = (const float*)d_in[3];
    float* out = (float*)d_out;

    int E  = in_sizes[1] / 2;
    int T4 = (E + 3) / 4;
    int S  = (T4 + 255) / 256;               // scatter blocks (first)
    int G  = (N_NODES + 127) / 128;          // gemm blocks

    fused_kernel<<<S + G, 256>>>(x, W1, W2, ei, E, S);
    dinv_kernel<<<(N_NODES + 255) / 256, 256>>>();
    agg_kernel<<<(N_NODES * 32 + 255) / 256, 256>>>(out);  // one warp per node
}